// round 1
// baseline (speedup 1.0000x reference)
#include <cuda_runtime.h>

// Cone-beam voxel-driven back-projection.
// Input : proj [B=2, 1, A=360, V=256, U=256] float32
// Output: vol  [B=2, 1, nz=128, ny=128, nx=128] float32
//
// Geometry (compile-time constants, match reference):
//   voxel size 2mm iso, det pixel 2mm, DSO=1000, DSD=1536.
//   iu = (yr*mag)/2 + 127.5,  iv = (z-63.5)*mag + 127.5,  mag = DSD/(DSO-xr)

#define NB   2
#define NA   360
#define NV   256
#define NU   256
#define NZ   128
#define NY   128
#define NX   128
#define ZC   16          // z-voxels per thread

#define DSO_F 1000.0f
#define DSD_F 1536.0f

// per-angle (cos, sin) table, filled by init kernel every launch (deterministic)
__device__ float2 g_cs[NA];

__global__ void bp_init_angles() {
    int a = threadIdx.x;
    if (a < NA) {
        // mimic jnp.linspace(0, 2pi, 360, endpoint=False) in f32
        const float step = 6.28318530717958647692f / 360.0f;
        float th = (float)a * step;
        float s, c;
        sincosf(th, &s, &c);
        g_cs[a] = make_float2(c, s);
    }
}

__global__ void __launch_bounds__(NX, 8)
bp_kernel(const float* __restrict__ proj, float* __restrict__ out) {
    const int x   = threadIdx.x;          // 0..127  (fastest, coalesced out)
    const int y   = blockIdx.x;           // 0..127
    const int zc0 = blockIdx.y * ZC;      // chunk start z
    const int b   = blockIdx.z;           // 0..1

    const float xcv = ((float)x - 63.5f) * 2.0f;
    const float ycv = ((float)y - 63.5f) * 2.0f;

    float acc[ZC];
#pragma unroll
    for (int k = 0; k < ZC; ++k) acc[k] = 0.0f;

    const float* __restrict__ pb = proj + (size_t)b * NA * NV * NU;

    for (int a = 0; a < NA; ++a) {
        const float2 cs = __ldg(&g_cs[a]);
        const float c = cs.x, s = cs.y;

        const float xr  = xcv * c + ycv * s;
        const float yr  = -xcv * s + ycv * c;
        const float mag = DSD_F / (DSO_F - xr);        // IEEE div (accurate)

        // iu = (yr*mag)/du + (U-1)/2 ; du = 2 => exact *0.5
        const float iu = (yr * mag) * 0.5f + 127.5f;
        if (!(iu >= 0.0f && iu <= 255.0f)) continue;   // whole column invalid in u

        const int   u0 = (int)floorf(iu);
        const int   u1 = min(u0 + 1, NU - 1);
        const float fu = iu - (float)u0;

        const float* __restrict__ pa = pb + (size_t)a * NV * NU;

#pragma unroll
        for (int k = 0; k < ZC; ++k) {
            // iv = zc*mag/dv + 127.5 = (iz-63.5)*mag + 127.5 (dz/dv = 1)
            const float zcv = (float)(zc0 + k) - 63.5f;
            const float iv  = zcv * mag + 127.5f;
            const bool  vv  = (iv >= 0.0f) && (iv <= 255.0f);

            const float ivc = fminf(fmaxf(iv, 0.0f), 255.0f);
            const int   v0  = (int)floorf(ivc);
            const int   v1  = min(v0 + 1, NV - 1);
            const float fv  = ivc - (float)v0;

            const float* r0 = pa + v0 * NU;
            const float* r1 = pa + v1 * NU;
            const float p00 = __ldg(r0 + u0);
            const float p01 = __ldg(r0 + u1);
            const float p10 = __ldg(r1 + u0);
            const float p11 = __ldg(r1 + u1);

            const float h0  = fmaf(fu, p01 - p00, p00);
            const float h1  = fmaf(fu, p11 - p10, p10);
            const float val = fmaf(fv, h1 - h0, h0);

            acc[k] += vv ? val : 0.0f;
        }
    }

    // store: out[((b*NZ + z)*NY + y)*NX + x], x contiguous -> coalesced
    const size_t base = (((size_t)b * NZ + zc0) * NY + y) * NX + x;
#pragma unroll
    for (int k = 0; k < ZC; ++k) {
        out[base + (size_t)k * NY * NX] = acc[k];
    }
}

extern "C" void kernel_launch(void* const* d_in, const int* in_sizes, int n_in,
                              void* d_out, int out_size) {
    (void)in_sizes; (void)n_in; (void)out_size;
    const float* proj = (const float*)d_in[0];
    float* out = (float*)d_out;

    bp_init_angles<<<1, NA>>>();

    dim3 grid(NY, NZ / ZC, NB);   // (128, 8, 2)
    dim3 block(NX);               // 128 threads
    bp_kernel<<<grid, block>>>(proj, out);
}

// round 2
// speedup vs baseline: 1.1057x; 1.1057x over previous
#include <cuda_runtime.h>

// Cone-beam voxel-driven back-projection.
// Input : proj [B=2, 1, A=360, V=256, U=256] float32
// Output: vol  [B=2, 1, nz=128, ny=128, nx=128] float32
//
//   iu = (yr*mag)*0.5 + 127.5,  iv = (z-63.5)*mag + 127.5,  mag = DSD/(DSO-xr)

#define NB   2
#define NA   360
#define NV   256
#define NU   256
#define NZ   128
#define NY   128
#define NX   128
#define ZC   16          // z-voxels per thread

#define DSO_F 1000.0f
#define DSD_F 1536.0f

// per-angle (cos, sin) table, filled by init kernel every launch (deterministic)
__device__ float2 g_cs[NA];

__global__ void bp_init_angles() {
    int a = threadIdx.x;
    if (a < NA) {
        const float step = 6.28318530717958647692f / 360.0f;
        float th = (float)a * step;
        float s, c;
        sincosf(th, &s, &c);
        g_cs[a] = make_float2(c, s);
    }
}

__global__ void __launch_bounds__(NX, 8)
bp_kernel(const float* __restrict__ proj, float* __restrict__ out) {
    const int x   = threadIdx.x;          // 0..127  (fastest, coalesced out)
    const int y   = blockIdx.x;           // 0..127
    const int zc0 = blockIdx.y * ZC;      // chunk start z
    const int b   = blockIdx.z;           // 0..1

    const float xcv = ((float)x - 63.5f) * 2.0f;   // mm
    const float ycv = ((float)y - 63.5f) * 2.0f;   // mm
    const float z0v = (float)zc0 - 63.5f;          // voxel units (dz/dv = 1)

    float acc[ZC];
#pragma unroll
    for (int k = 0; k < ZC; ++k) acc[k] = 0.0f;

    const float* __restrict__ pb = proj + (size_t)b * NA * NV * NU;

    for (int a = 0; a < NA; ++a) {
        const float2 cs = __ldg(&g_cs[a]);
        const float c = cs.x, s = cs.y;

        const float xr  = xcv * c + ycv * s;
        const float yr  = -xcv * s + ycv * c;
        const float mag = DSD_F / (DSO_F - xr);        // IEEE div, mag > 0

        // u coordinate is z-invariant: whole column shares it
        const float iu = (yr * mag) * 0.5f + 127.5f;
        if (!(iu >= 0.0f && iu <= 255.0f)) continue;   // column invalid in u

        const int   u0 = (int)iu;                      // iu>=0 -> trunc == floor
        const int   u1 = min(u0 + 1, NU - 1);
        const float fu = iu - (float)u0;

        // iv(k) = (z0v + k)*mag + 127.5, strictly increasing in k
        const float iv_first = z0v * mag + 127.5f;
        const float iv_last  = iv_first + (float)(ZC - 1) * mag;
        if (iv_last < 0.0f || iv_first > 255.0f) continue;  // whole chunk misses detector

        const float* __restrict__ pa  = pb + (size_t)a * NV * NU;
        const float* __restrict__ pu0 = pa + u0;
        const float* __restrict__ pu1 = pa + u1;

#pragma unroll
        for (int k = 0; k < ZC; ++k) {
            const float iv = fmaf(z0v + (float)k, mag, 127.5f);
            if (iv >= 0.0f && iv <= 255.0f) {
                const int   v0   = (int)iv;            // floor (iv>=0)
                const int   v1   = min(v0 + 1, NV - 1);
                const float fv   = iv - (float)v0;
                const int   off0 = v0 << 8;            // v0*NU
                const int   off1 = v1 << 8;

                const float p00 = __ldg(pu0 + off0);
                const float p01 = __ldg(pu1 + off0);
                const float p10 = __ldg(pu0 + off1);
                const float p11 = __ldg(pu1 + off1);

                const float h0 = fmaf(fu, p01 - p00, p00);
                const float h1 = fmaf(fu, p11 - p10, p10);
                acc[k] += fmaf(fv, h1 - h0, h0);
            }
        }
    }

    // store: out[((b*NZ + z)*NY + y)*NX + x], x contiguous -> coalesced
    const size_t base = (((size_t)b * NZ + zc0) * NY + y) * NX + x;
#pragma unroll
    for (int k = 0; k < ZC; ++k) {
        out[base + (size_t)k * NY * NX] = acc[k];
    }
}

extern "C" void kernel_launch(void* const* d_in, const int* in_sizes, int n_in,
                              void* d_out, int out_size) {
    (void)in_sizes; (void)n_in; (void)out_size;
    const float* proj = (const float*)d_in[0];
    float* out = (float*)d_out;

    bp_init_angles<<<1, NA>>>();

    dim3 grid(NY, NZ / ZC, NB);   // (128, 8, 2)
    dim3 block(NX);               // 128 threads
    bp_kernel<<<grid, block>>>(proj, out);
}

// round 5
// speedup vs baseline: 2.2828x; 2.0645x over previous
#include <cuda_runtime.h>

// Cone-beam voxel-driven back-projection.
// Input : proj [B=2, 1, A=360, V=256, U=256] float32
// Output: vol  [B=2, 1, nz=128, ny=128, nx=128] float32
//
//   iu = (yr*mag)*0.5 + 127.5,  iv = (z-63.5)*mag + 127.5,  mag = DSD/(DSO-xr)

#define NB   2
#define NA   360
#define NV   256
#define NU   256
#define NZ   128
#define NY   128
#define NX   128
#define ZC   16          // z-voxels per thread
#define SC   8           // staging sub-chunk (loads batched per SC taps)

#define DSO_F 1000.0f
#define DSD_F 1536.0f

// per-angle (cos, sin) table, filled by init kernel every launch (deterministic)
__device__ float2 g_cs[NA];

__global__ void bp_init_angles() {
    int a = threadIdx.x;
    if (a < NA) {
        const float step = 6.28318530717958647692f / 360.0f;
        float th = (float)a * step;
        float s, c;
        sincosf(th, &s, &c);
        g_cs[a] = make_float2(c, s);
    }
}

__global__ void __launch_bounds__(NX, 6)
bp_kernel(const float* __restrict__ proj, float* __restrict__ out) {
    const int x   = threadIdx.x;          // 0..127  (fastest, coalesced out)
    const int y   = blockIdx.x;           // 0..127
    const int zc0 = blockIdx.y * ZC;      // chunk start z
    const int b   = blockIdx.z;           // 0..1

    const float xcv = ((float)x - 63.5f) * 2.0f;   // mm
    const float ycv = ((float)y - 63.5f) * 2.0f;   // mm
    const float z0v = (float)zc0 - 63.5f;          // voxel units (dz/dv = 1)

    float acc[ZC];
#pragma unroll
    for (int k = 0; k < ZC; ++k) acc[k] = 0.0f;

    const float* __restrict__ pb = proj + (size_t)b * NA * NV * NU;

    for (int a = 0; a < NA; ++a) {
        const float2 cs = __ldg(&g_cs[a]);
        const float c = cs.x, s = cs.y;

        const float xr  = xcv * c + ycv * s;
        const float yr  = -xcv * s + ycv * c;
        const float mag = DSD_F / (DSO_F - xr);        // IEEE div, mag > 0

        // u coordinate is z-invariant: whole column shares it
        const float iu = (yr * mag) * 0.5f + 127.5f;
        if (!(iu >= 0.0f && iu <= 255.0f)) continue;   // column invalid in u

        // iv(k) = iv_first + k*mag, strictly increasing in k
        const float iv_first = fmaf(z0v, mag, 127.5f);
        const float iv_last  = fmaf((float)(ZC - 1), mag, iv_first);
        if (iv_last < 0.0f || iv_first > 255.0f) continue;  // whole chunk misses detector

        const int   u0 = (int)iu;                      // iu>=0 -> trunc == floor
        const float fu = iu - (float)u0;
        const float* __restrict__ pa = pb + (size_t)a * NV * NU;

        if (iu < 255.0f && iv_first >= 0.0f && iv_last < 255.0f) {
            // ---- FAST PATH: every tap valid, no clamps, batched loads ----
            const float* __restrict__ p0 = pa + u0;    // u1 = u0+1 guaranteed
#pragma unroll
            for (int h = 0; h < ZC / SC; ++h) {
                float p00[SC], p01[SC], p10[SC], p11[SC], fvv[SC];
#pragma unroll
                for (int k = 0; k < SC; ++k) {
                    const int   kk = h * SC + k;
                    const float iv = fmaf((float)kk, mag, iv_first);
                    const int   v0 = (int)iv;          // floor (iv>=0), v0<=254
                    fvv[k] = iv - (float)v0;
                    const float* __restrict__ r0 = p0 + (v0 << 8);
                    p00[k] = __ldg(r0);
                    p01[k] = __ldg(r0 + 1);
                    p10[k] = __ldg(r0 + NU);
                    p11[k] = __ldg(r0 + NU + 1);
                }
#pragma unroll
                for (int k = 0; k < SC; ++k) {
                    const float h0 = fmaf(fu, p01[k] - p00[k], p00[k]);
                    const float h1 = fmaf(fu, p11[k] - p10[k], p10[k]);
                    acc[h * SC + k] += fmaf(fvv[k], h1 - h0, h0);
                }
            }
        } else {
            // ---- SLOW PATH: detector edge, per-tap guards & clamps ----
            const int u1 = min(u0 + 1, NU - 1);
            const float* __restrict__ pu0 = pa + u0;
            const float* __restrict__ pu1 = pa + u1;
#pragma unroll
            for (int k = 0; k < ZC; ++k) {
                const float iv = fmaf((float)k, mag, iv_first);
                if (iv >= 0.0f && iv <= 255.0f) {
                    const int   v0   = (int)iv;
                    const int   v1   = min(v0 + 1, NV - 1);
                    const float fv   = iv - (float)v0;
                    const int   off0 = v0 << 8;
                    const int   off1 = v1 << 8;

                    const float p00 = __ldg(pu0 + off0);
                    const float p01 = __ldg(pu1 + off0);
                    const float p10 = __ldg(pu0 + off1);
                    const float p11 = __ldg(pu1 + off1);

                    const float h0 = fmaf(fu, p01 - p00, p00);
                    const float h1 = fmaf(fu, p11 - p10, p10);
                    acc[k] += fmaf(fv, h1 - h0, h0);
                }
            }
        }
    }

    // store: out[((b*NZ + z)*NY + y)*NX + x], x contiguous -> coalesced
    const size_t base = (((size_t)b * NZ + zc0) * NY + y) * NX + x;
#pragma unroll
    for (int k = 0; k < ZC; ++k) {
        out[base + (size_t)k * NY * NX] = acc[k];
    }
}

extern "C" void kernel_launch(void* const* d_in, const int* in_sizes, int n_in,
                              void* d_out, int out_size) {
    (void)in_sizes; (void)n_in; (void)out_size;
    const float* proj = (const float*)d_in[0];
    float* out = (float*)d_out;

    bp_init_angles<<<1, NA>>>();

    dim3 grid(NY, NZ / ZC, NB);   // (128, 8, 2)
    dim3 block(NX);               // 128 threads
    bp_kernel<<<grid, block>>>(proj, out);
}

// round 7
// speedup vs baseline: 3.0395x; 1.3315x over previous
#include <cuda_runtime.h>

// Cone-beam voxel-driven back-projection.
// Input : proj [B=2, 1, A=360, V=256, U=256] float32
// Output: vol  [B=2, 1, nz=128, ny=128, nx=128] float32
//
//   iu = (yr*mag)*0.5 + 127.5,  iv = (z-63.5)*mag + 127.5,  mag = DSD/(DSO-xr)
//
// Warp footprint: 8x by 4y tile (block 8x16) so each warp's detector
// access window stays within ~1-2 cache lines per LDG for every angle.

#define NB   2
#define NA   360
#define NV   256
#define NU   256
#define NZ   128
#define NY   128
#define NX   128
#define ZC   16          // z-voxels per thread
#define SC   8           // staging sub-chunk (loads batched per SC taps)
#define TX   8           // x per block
#define TY   16          // y per block

#define DSO_F 1000.0f
#define DSD_F 1536.0f

// per-angle (cos, sin) table, filled by init kernel every launch (deterministic)
__device__ float2 g_cs[NA];

__global__ void bp_init_angles() {
    int a = threadIdx.x;
    if (a < NA) {
        const float step = 6.28318530717958647692f / 360.0f;
        float th = (float)a * step;
        float s, c;
        sincosf(th, &s, &c);
        g_cs[a] = make_float2(c, s);
    }
}

__global__ void __launch_bounds__(TX * TY, 6)
bp_kernel(const float* __restrict__ proj, float* __restrict__ out) {
    const int x   = blockIdx.x * TX + threadIdx.x;   // 0..127
    const int y   = blockIdx.y * TY + threadIdx.y;   // 0..127
    const int zc0 = (blockIdx.z & 7) * ZC;           // chunk start z
    const int b   = blockIdx.z >> 3;                 // 0..1

    const float xcv = ((float)x - 63.5f) * 2.0f;   // mm
    const float ycv = ((float)y - 63.5f) * 2.0f;   // mm
    const float z0v = (float)zc0 - 63.5f;          // voxel units (dz/dv = 1)

    float acc[ZC];
#pragma unroll
    for (int k = 0; k < ZC; ++k) acc[k] = 0.0f;

    const float* __restrict__ pb = proj + (size_t)b * NA * NV * NU;

    for (int a = 0; a < NA; ++a) {
        const float2 cs = __ldg(&g_cs[a]);
        const float c = cs.x, s = cs.y;

        const float xr  = xcv * c + ycv * s;
        const float yr  = -xcv * s + ycv * c;
        const float mag = DSD_F / (DSO_F - xr);        // IEEE div, mag > 0

        // u coordinate is z-invariant: whole column shares it
        const float iu = (yr * mag) * 0.5f + 127.5f;
        if (!(iu >= 0.0f && iu <= 255.0f)) continue;   // column invalid in u

        // iv(k) = iv_first + k*mag, strictly increasing in k
        const float iv_first = fmaf(z0v, mag, 127.5f);
        const float iv_last  = fmaf((float)(ZC - 1), mag, iv_first);
        if (iv_last < 0.0f || iv_first > 255.0f) continue;  // whole chunk misses detector

        const int   u0 = (int)iu;                      // iu>=0 -> trunc == floor
        const float fu = iu - (float)u0;
        const float* __restrict__ pa = pb + (size_t)a * NV * NU;

        if (iu < 255.0f && iv_first >= 0.0f && iv_last < 255.0f) {
            // ---- FAST PATH: every tap valid, no clamps, batched loads ----
            const float* __restrict__ p0 = pa + u0;    // u1 = u0+1 guaranteed
#pragma unroll
            for (int h = 0; h < ZC / SC; ++h) {
                float p00[SC], p01[SC], p10[SC], p11[SC], fvv[SC];
#pragma unroll
                for (int k = 0; k < SC; ++k) {
                    const int   kk = h * SC + k;
                    const float iv = fmaf((float)kk, mag, iv_first);
                    const int   v0 = (int)iv;          // floor (iv>=0), v0<=254
                    fvv[k] = iv - (float)v0;
                    const float* __restrict__ r0 = p0 + (v0 << 8);
                    p00[k] = __ldg(r0);
                    p01[k] = __ldg(r0 + 1);
                    p10[k] = __ldg(r0 + NU);
                    p11[k] = __ldg(r0 + NU + 1);
                }
#pragma unroll
                for (int k = 0; k < SC; ++k) {
                    const float h0 = fmaf(fu, p01[k] - p00[k], p00[k]);
                    const float h1 = fmaf(fu, p11[k] - p10[k], p10[k]);
                    acc[h * SC + k] += fmaf(fvv[k], h1 - h0, h0);
                }
            }
        } else {
            // ---- SLOW PATH: detector edge, per-tap guards & clamps ----
            const int u1 = min(u0 + 1, NU - 1);
            const float* __restrict__ pu0 = pa + u0;
            const float* __restrict__ pu1 = pa + u1;
#pragma unroll
            for (int k = 0; k < ZC; ++k) {
                const float iv = fmaf((float)k, mag, iv_first);
                if (iv >= 0.0f && iv <= 255.0f) {
                    const int   v0   = (int)iv;
                    const int   v1   = min(v0 + 1, NV - 1);
                    const float fv   = iv - (float)v0;
                    const int   off0 = v0 << 8;
                    const int   off1 = v1 << 8;

                    const float p00 = __ldg(pu0 + off0);
                    const float p01 = __ldg(pu1 + off0);
                    const float p10 = __ldg(pu0 + off1);
                    const float p11 = __ldg(pu1 + off1);

                    const float h0 = fmaf(fu, p01 - p00, p00);
                    const float h1 = fmaf(fu, p11 - p10, p10);
                    acc[k] += fmaf(fv, h1 - h0, h0);
                }
            }
        }
    }

    // store: out[((b*NZ + z)*NY + y)*NX + x]
    const size_t base = (((size_t)b * NZ + zc0) * NY + y) * NX + x;
#pragma unroll
    for (int k = 0; k < ZC; ++k) {
        out[base + (size_t)k * NY * NX] = acc[k];
    }
}

extern "C" void kernel_launch(void* const* d_in, const int* in_sizes, int n_in,
                              void* d_out, int out_size) {
    (void)in_sizes; (void)n_in; (void)out_size;
    const float* proj = (const float*)d_in[0];
    float* out = (float*)d_out;

    bp_init_angles<<<1, NA>>>();

    dim3 grid(NX / TX, NY / TY, (NZ / ZC) * NB);   // (16, 8, 16)
    dim3 block(TX, TY);                            // 128 threads, warp = 8x*4y
    bp_kernel<<<grid, block>>>(proj, out);
}